// round 2
// baseline (speedup 1.0000x reference)
#include <cuda_runtime.h>
#include <cstdint>

#define NB 64
#define NS 2048
#define ND 512
#define NU 512

// Scratch (allocation-free rule: __device__ globals)
__device__ float g_d[NB * NU];        // proj_dec + b1 + b2
__device__ float g_scores[NB * NS];   // raw scores before softmax

__device__ __forceinline__ float to_tf32(float x) {
    asm("cvt.rna.tf32.f32 %0, %0;" : "+f"(x));
    return x;
}

// Accurate tanh: clamp + exp-based, rel err ~1e-6 (2 MUFU)
__device__ __forceinline__ float fast_tanh(float x) {
    x = fminf(fmaxf(x, -9.0f), 9.0f);
    float e = __expf(2.0f * x);
    return __fdividef(e - 1.0f, e + 1.0f);
}

__device__ __forceinline__ void mma_tf32(float d[4], const uint32_t a[4],
                                         uint32_t b0, uint32_t b1) {
    asm volatile(
        "mma.sync.aligned.m16n8k8.row.col.f32.tf32.tf32.f32 "
        "{%0,%1,%2,%3}, {%4,%5,%6,%7}, {%8,%9}, {%0,%1,%2,%3};\n"
        : "+f"(d[0]), "+f"(d[1]), "+f"(d[2]), "+f"(d[3])
        : "r"(a[0]), "r"(a[1]), "r"(a[2]), "r"(a[3]), "r"(b0), "r"(b1));
}

// ---------------- Kernel 1: d[b,u] = dec[b]@W2 + b1 + b2 ----------------
__global__ void dec_proj_kernel(const float* __restrict__ dec,
                                const float* __restrict__ W2,
                                const float* __restrict__ b1,
                                const float* __restrict__ b2) {
    int b = blockIdx.x, tid = threadIdx.x;
    __shared__ float ds[ND];
    ds[tid]       = dec[b * ND + tid];
    ds[tid + 256] = dec[b * ND + tid + 256];
    __syncthreads();
    int u0 = tid, u1 = tid + 256;
    float a0 = b1[u0] + b2[u0];
    float a1 = b1[u1] + b2[u1];
#pragma unroll 8
    for (int k = 0; k < ND; k++) {
        float dv = ds[k];
        a0 += dv * W2[k * NU + u0];
        a1 += dv * W2[k * NU + u1];
    }
    g_d[b * NU + u0] = a0;
    g_d[b * NU + u1] = a1;
}

// ---------------- Kernel 2: fused enc@W1 -> tanh -> dot(V) -> score ----------------
// Grid: 1024 CTAs (128 rows each). Block: 256 threads = 8 warps (4 in M, 2 in N).
// Warp tile: 32 (M) x 64 (N) via m16n8k8 tf32 MMA; N looped in 4 chunks of 128.
__global__ __launch_bounds__(256, 2) void score_kernel(
    const float* __restrict__ enc, const float* __restrict__ W1,
    const float* __restrict__ V) {
    // Pads chosen for conflict-free fragment LDS:
    //  As stride 36 (36 mod 32 = 4 -> bank = 4*grp + t, injective)
    //  Bs stride 136 (136 mod 32 = 8 -> bank = 8*t + grp, injective)
    __shared__ __align__(16) float As[128][36];
    __shared__ __align__(16) float Bs[32][136];
    __shared__ float dsh[NU], vsh[NU], spart[2][128];

    const int tid  = threadIdx.x;
    const int row0 = blockIdx.x * 128;
    const int b    = blockIdx.x >> 4;   // 16 row-tiles per batch element

    dsh[tid]       = g_d[b * NU + tid];
    dsh[tid + 256] = g_d[b * NU + tid + 256];
    vsh[tid]       = V[tid];
    vsh[tid + 256] = V[tid + 256];
    if (tid < 128) { spart[0][tid] = 0.0f; spart[1][tid] = 0.0f; }

    const int warp = tid >> 5, lane = tid & 31;
    const int wm = warp & 3, wn = warp >> 2;
    const int grp = lane >> 2, t = lane & 3;
    const int mBase = wm * 32;
    const int nBase = wn * 64;

    for (int nc = 0; nc < 4; nc++) {
        float acc[2][8][4];
#pragma unroll
        for (int i = 0; i < 2; i++)
#pragma unroll
            for (int j = 0; j < 8; j++)
#pragma unroll
                for (int e = 0; e < 4; e++) acc[i][j][e] = 0.0f;

        for (int kb = 0; kb < ND; kb += 32) {
            __syncthreads();
            // Load A tile: 128 rows x 32 cols of enc (tf32-rounded)
#pragma unroll
            for (int i = 0; i < 4; i++) {
                int j = tid + 256 * i;
                int r = j >> 3, c4 = j & 7;
                float4 v = *reinterpret_cast<const float4*>(
                    &enc[(size_t)(row0 + r) * ND + kb + c4 * 4]);
                v.x = to_tf32(v.x); v.y = to_tf32(v.y);
                v.z = to_tf32(v.z); v.w = to_tf32(v.w);
                *reinterpret_cast<float4*>(&As[r][c4 * 4]) = v;
            }
            // Load B tile: 32 rows (k) x 128 cols (u) of W1
#pragma unroll
            for (int i = 0; i < 4; i++) {
                int j = tid + 256 * i;
                int r = j >> 5, c4 = j & 31;
                float4 v = *reinterpret_cast<const float4*>(
                    &W1[(size_t)(kb + r) * NU + nc * 128 + c4 * 4]);
                v.x = to_tf32(v.x); v.y = to_tf32(v.y);
                v.z = to_tf32(v.z); v.w = to_tf32(v.w);
                *reinterpret_cast<float4*>(&Bs[r][c4 * 4]) = v;
            }
            __syncthreads();

#pragma unroll
            for (int ks = 0; ks < 4; ks++) {
                const int k0 = ks * 8;
                uint32_t a[2][4];
#pragma unroll
                for (int mt = 0; mt < 2; mt++) {
                    int mr = mBase + mt * 16 + grp;
                    a[mt][0] = __float_as_uint(As[mr][k0 + t]);
                    a[mt][1] = __float_as_uint(As[mr + 8][k0 + t]);
                    a[mt][2] = __float_as_uint(As[mr][k0 + t + 4]);
                    a[mt][3] = __float_as_uint(As[mr + 8][k0 + t + 4]);
                }
#pragma unroll
                for (int nt = 0; nt < 8; nt++) {
                    int ncc = nBase + nt * 8 + grp;
                    uint32_t b0 = __float_as_uint(Bs[k0 + t][ncc]);
                    uint32_t b1 = __float_as_uint(Bs[k0 + t + 4][ncc]);
                    mma_tf32(acc[0][nt], a[0], b0, b1);
                    mma_tf32(acc[1][nt], a[1], b0, b1);
                }
            }
        }

        // Epilogue: partial score += sum_u tanh(proj + d[b,u]) * V[u]
        float rs[2][2] = {{0.0f, 0.0f}, {0.0f, 0.0f}};
#pragma unroll
        for (int nt = 0; nt < 8; nt++) {
#pragma unroll
            for (int e = 0; e < 4; e++) {
                int u = nc * 128 + nBase + nt * 8 + 2 * t + (e & 1);
                float dv = dsh[u];
                float vv = vsh[u];
                int h = e >> 1;
                rs[0][h] += fast_tanh(acc[0][nt][e] + dv) * vv;
                rs[1][h] += fast_tanh(acc[1][nt][e] + dv) * vv;
            }
        }
#pragma unroll
        for (int mt = 0; mt < 2; mt++)
#pragma unroll
            for (int h = 0; h < 2; h++) {
                float v = rs[mt][h];
                v += __shfl_xor_sync(0xffffffffu, v, 1);
                v += __shfl_xor_sync(0xffffffffu, v, 2);
                if (t == 0) {
                    int r = mBase + mt * 16 + grp + h * 8;
                    spart[wn][r] += v;   // unique owner warp, no race
                }
            }
    }
    __syncthreads();
    if (tid < 128)
        g_scores[row0 + tid] = spart[0][tid] + spart[1][tid];
}

// ---------------- Kernel 3: softmax over S per batch row ----------------
__global__ void softmax_kernel(float* __restrict__ attn_out) {
    int b = blockIdx.x, tid = threadIdx.x;
    __shared__ float red[256];
    float v[8];
    float m = -1e30f;
#pragma unroll
    for (int i = 0; i < 8; i++) {
        v[i] = g_scores[b * NS + tid + 256 * i];
        m = fmaxf(m, v[i]);
    }
    red[tid] = m;
    __syncthreads();
    for (int s = 128; s > 0; s >>= 1) {
        if (tid < s) red[tid] = fmaxf(red[tid], red[tid + s]);
        __syncthreads();
    }
    m = red[0];
    __syncthreads();
    float sum = 0.0f;
#pragma unroll
    for (int i = 0; i < 8; i++) {
        v[i] = __expf(v[i] - m);
        sum += v[i];
    }
    red[tid] = sum;
    __syncthreads();
    for (int s = 128; s > 0; s >>= 1) {
        if (tid < s) red[tid] += red[tid + s];
        __syncthreads();
    }
    float inv = 1.0f / red[0];
#pragma unroll
    for (int i = 0; i < 8; i++)
        attn_out[b * NS + tid + 256 * i] = v[i] * inv;
}

// ---------------- Kernel 4: context[b,:] = attn[b,:] @ enc[b] ----------------
// Grid (4 d-chunks, 64 b). Block 256: 32 lanes x float4 over d, 8 s-strides.
__global__ void context_kernel(const float* __restrict__ enc,
                               const float* __restrict__ attn,
                               float* __restrict__ ctx) {
    int dc = blockIdx.x, b = blockIdx.y;
    int tid = threadIdx.x;
    int lx = tid & 31;    // d-group
    int ty = tid >> 5;    // 0..7 s-stride
    __shared__ float att[NS];
    __shared__ float4 redc[7][32];
#pragma unroll
    for (int i = 0; i < 8; i++) att[tid + 256 * i] = attn[b * NS + tid + 256 * i];
    __syncthreads();
    int d0 = dc * 128 + lx * 4;
    const float* base = enc + (size_t)b * NS * ND + d0;
    float4 acc = {0.0f, 0.0f, 0.0f, 0.0f};
#pragma unroll 4
    for (int s = ty; s < NS; s += 8) {
        float a = att[s];
        float4 v = *reinterpret_cast<const float4*>(base + (size_t)s * ND);
        acc.x += a * v.x; acc.y += a * v.y;
        acc.z += a * v.z; acc.w += a * v.w;
    }
    if (ty > 0) redc[ty - 1][lx] = acc;
    __syncthreads();
    if (ty == 0) {
#pragma unroll
        for (int i = 0; i < 7; i++) {
            float4 r = redc[i][lx];
            acc.x += r.x; acc.y += r.y; acc.z += r.z; acc.w += r.w;
        }
        *reinterpret_cast<float4*>(&ctx[b * ND + d0]) = acc;
    }
}

extern "C" void kernel_launch(void* const* d_in, const int* in_sizes, int n_in,
                              void* d_out, int out_size) {
    const float* enc = (const float*)d_in[0];
    const float* dec = (const float*)d_in[1];
    const float* W1  = (const float*)d_in[2];
    const float* b1  = (const float*)d_in[3];
    const float* W2  = (const float*)d_in[4];
    const float* b2  = (const float*)d_in[5];
    const float* V   = (const float*)d_in[6];
    // d_in[7] = bv: softmax is shift-invariant and raw score is not an output -> unused.

    float* ctx  = (float*)d_out;             // [64, 512] first (tuple order)
    float* attn = (float*)d_out + NB * ND;   // [64, 2048]

    dec_proj_kernel<<<NB, 256>>>(dec, W2, b1, b2);
    score_kernel<<<(NB * NS) / 128, 256>>>(enc, W1, V);
    softmax_kernel<<<NB, 256>>>(attn);
    context_kernel<<<dim3(4, NB), 256>>>(enc, attn, ctx);
}

// round 4
// speedup vs baseline: 1.2291x; 1.2291x over previous
#include <cuda_runtime.h>
#include <cstdint>

#define NB 64
#define NS 2048
#define ND 512
#define NU 512

// -------- scratch (__device__ globals; allocation-free rule) --------
__device__ float g_d[NB * NU];          // dec proj + b1 + b2
__device__ float g_scores[NB * NS];     // raw scores
__device__ float g_W1r[ND * NU];        // W1 rounded to tf32 (RNA), same layout
__device__ float g_cpart[4][NB * ND];   // context partials over s-chunks

__device__ __forceinline__ float to_tf32(float x) {
    asm("cvt.rna.tf32.f32 %0, %0;" : "+f"(x));
    return x;
}
__device__ __forceinline__ float fast_tanh(float x) {
    x = fminf(fmaxf(x, -9.0f), 9.0f);
    float e = __expf(2.0f * x);
    return __fdividef(e - 1.0f, e + 1.0f);
}
__device__ __forceinline__ uint32_t smem_u32(const void* p) {
    uint32_t a;
    asm("{ .reg .u64 t; cvta.to.shared.u64 t, %1; cvt.u32.u64 %0, t; }"
        : "=r"(a) : "l"(p));
    return a;
}
__device__ __forceinline__ void cp16(uint32_t s, const void* g) {
    asm volatile("cp.async.cg.shared.global [%0], [%1], 16;"
                 :: "r"(s), "l"(g));
}
__device__ __forceinline__ void cp_commit() {
    asm volatile("cp.async.commit_group;");
}
__device__ __forceinline__ void cp_wait_all() {
    asm volatile("cp.async.wait_group 0;");
}
__device__ __forceinline__ void mma_tf32(float d[4], const uint32_t a[4],
                                         uint32_t b0, uint32_t b1) {
    asm volatile(
        "mma.sync.aligned.m16n8k8.row.col.f32.tf32.tf32.f32 "
        "{%0,%1,%2,%3}, {%4,%5,%6,%7}, {%8,%9}, {%0,%1,%2,%3};\n"
        : "+f"(d[0]), "+f"(d[1]), "+f"(d[2]), "+f"(d[3])
        : "r"(a[0]), "r"(a[1]), "r"(a[2]), "r"(a[3]), "r"(b0), "r"(b1));
}

// -------- dynamic SMEM layout for score kernel (float offsets) --------
// As: 2 stages x [128][36]  (row stride 144B, 16B aligned; bank-injective)
// Bs: 2 stages x [32][136]  (row stride 544B, 16B aligned; bank-injective)
#define A_F      0
#define A_STAGE  4608       // 128*36
#define B_F      9216
#define B_STAGE  4352       // 32*136
#define DSH_F    17920
#define VSH_F    18432
#define SPART_F  18944
#define SMEM_F   19200
#define SMEM_BYTES (SMEM_F * 4)

// ---------------- Kernel 0: round W1 to tf32 (RNA) ----------------
__global__ void round_w1(const float* __restrict__ W1) {
    int i = (blockIdx.x * 256 + threadIdx.x) * 4;
    float4 v = *reinterpret_cast<const float4*>(&W1[i]);
    v.x = to_tf32(v.x); v.y = to_tf32(v.y);
    v.z = to_tf32(v.z); v.w = to_tf32(v.w);
    *reinterpret_cast<float4*>(&g_W1r[i]) = v;
}

// ---------------- Kernel 1: d[b,u] = dec[b]@W2 + b1 + b2 ----------------
__global__ void dec_proj_kernel(const float* __restrict__ dec,
                                const float* __restrict__ W2,
                                const float* __restrict__ b1,
                                const float* __restrict__ b2) {
    int b = blockIdx.x, tid = threadIdx.x;
    __shared__ float ds[ND];
    ds[tid]       = dec[b * ND + tid];
    ds[tid + 256] = dec[b * ND + tid + 256];
    __syncthreads();
    int u0 = tid, u1 = tid + 256;
    float a0 = b1[u0] + b2[u0];
    float a1 = b1[u1] + b2[u1];
#pragma unroll 8
    for (int k = 0; k < ND; k++) {
        float dv = ds[k];
        a0 += dv * W2[k * NU + u0];
        a1 += dv * W2[k * NU + u1];
    }
    g_d[b * NU + u0] = a0;
    g_d[b * NU + u1] = a1;
}

// ---------------- Kernel 2: fused score, cp.async 2-stage pipeline ----------------
// 1024 CTAs x 256 thr (8 warps: 4 in M x 2 in N). Warp tile 32x64.
// A = raw fp32 enc via cp.async (HMMA.TF32 truncates low 13 bits);
// B = pre-rounded g_W1r via cp.async.
__global__ __launch_bounds__(256, 2) void score_kernel(
    const float* __restrict__ enc, const float* __restrict__ V) {
    extern __shared__ __align__(16) float smf[];
    const uint32_t sbase = smem_u32(smf);

    const int tid  = threadIdx.x;
    const int warp = tid >> 5, lane = tid & 31;
    const int row0 = blockIdx.x * 128;
    const int b    = blockIdx.x >> 4;

    float* dsh   = smf + DSH_F;
    float* vsh   = smf + VSH_F;
    float* spart = smf + SPART_F;
    dsh[tid]       = g_d[b * NU + tid];
    dsh[tid + 256] = g_d[b * NU + tid + 256];
    vsh[tid]       = V[tid];
    vsh[tid + 256] = V[tid + 256];
    if (tid < 256) spart[tid] = 0.0f;

    const int wm = warp & 3, wn = warp >> 2;
    const int grp = lane >> 2, t = lane & 3;
    const int mBase = wm * 32;
    const int nBase = wn * 64;

    // Per-thread copy coordinates (4 x 16B chunks per tile per thread)
    const int ar = tid >> 3, ac = tid & 7;     // + i*32 rows
    const int br = tid >> 5, bc = tid & 31;    // + i*8 rows
    __syncthreads();

    for (int nc = 0; nc < 4; nc++) {
        float acc[2][8][4];
#pragma unroll
        for (int i = 0; i < 2; i++)
#pragma unroll
            for (int j = 0; j < 8; j++)
#pragma unroll
                for (int e = 0; e < 4; e++) acc[i][j][e] = 0.0f;

        // Prologue: issue tile kb=0 into stage 0
        {
            uint32_t aB = sbase + (A_F) * 4;
            uint32_t bB = sbase + (B_F) * 4;
#pragma unroll
            for (int i = 0; i < 4; i++) {
                int r = ar + i * 32;
                cp16(aB + r * 144 + ac * 16,
                     enc + (size_t)(row0 + r) * ND + ac * 4);
            }
#pragma unroll
            for (int i = 0; i < 4; i++) {
                int r = br + i * 8;
                cp16(bB + r * 544 + bc * 16,
                     g_W1r + (size_t)r * NU + nc * 128 + bc * 4);
            }
            cp_commit();
        }

        for (int kb = 0; kb < 16; kb++) {
            const int cur = kb & 1;
            cp_wait_all();
            __syncthreads();
            if (kb < 15) {
                const int nxt = cur ^ 1;
                const int kk = (kb + 1) * 32;
                uint32_t aB = sbase + (A_F + nxt * A_STAGE) * 4;
                uint32_t bB = sbase + (B_F + nxt * B_STAGE) * 4;
#pragma unroll
                for (int i = 0; i < 4; i++) {
                    int r = ar + i * 32;
                    cp16(aB + r * 144 + ac * 16,
                         enc + (size_t)(row0 + r) * ND + kk + ac * 4);
                }
#pragma unroll
                for (int i = 0; i < 4; i++) {
                    int r = br + i * 8;
                    cp16(bB + r * 544 + bc * 16,
                         g_W1r + (size_t)(kk + r) * NU + nc * 128 + bc * 4);
                }
                cp_commit();
            }
            const float* Asb = smf + A_F + cur * A_STAGE;
            const float* Bsb = smf + B_F + cur * B_STAGE;
#pragma unroll
            for (int ks = 0; ks < 4; ks++) {
                const int k0 = ks * 8;
                uint32_t a[2][4];
#pragma unroll
                for (int mt = 0; mt < 2; mt++) {
                    int mr = mBase + mt * 16 + grp;
                    a[mt][0] = __float_as_uint(Asb[mr * 36 + k0 + t]);
                    a[mt][1] = __float_as_uint(Asb[(mr + 8) * 36 + k0 + t]);
                    a[mt][2] = __float_as_uint(Asb[mr * 36 + k0 + t + 4]);
                    a[mt][3] = __float_as_uint(Asb[(mr + 8) * 36 + k0 + t + 4]);
                }
#pragma unroll
                for (int nt = 0; nt < 8; nt++) {
                    int ncc = nBase + nt * 8 + grp;
                    uint32_t b0 = __float_as_uint(Bsb[(k0 + t) * 136 + ncc]);
                    uint32_t b1 = __float_as_uint(Bsb[(k0 + t + 4) * 136 + ncc]);
                    mma_tf32(acc[0][nt], a[0], b0, b1);
                    mma_tf32(acc[1][nt], a[1], b0, b1);
                }
            }
        }

        // Epilogue: partial score += sum_u tanh(proj + d[b,u]) * V[u]
        float rs[2][2] = {{0.0f, 0.0f}, {0.0f, 0.0f}};
#pragma unroll
        for (int nt = 0; nt < 8; nt++) {
#pragma unroll
            for (int e = 0; e < 4; e++) {
                int u = nc * 128 + nBase + nt * 8 + 2 * t + (e & 1);
                float dv = dsh[u];
                float vv = vsh[u];
                int h = e >> 1;
                rs[0][h] += fast_tanh(acc[0][nt][e] + dv) * vv;
                rs[1][h] += fast_tanh(acc[1][nt][e] + dv) * vv;
            }
        }
#pragma unroll
        for (int mt = 0; mt < 2; mt++)
#pragma unroll
            for (int h = 0; h < 2; h++) {
                float v = rs[mt][h];
                v += __shfl_xor_sync(0xffffffffu, v, 1);
                v += __shfl_xor_sync(0xffffffffu, v, 2);
                if (t == 0) {
                    int r = mBase + mt * 16 + grp + h * 8;
                    spart[wn * 128 + r] += v;  // unique owner warp, no race
                }
            }
    }
    __syncthreads();
    if (tid < 128)
        g_scores[row0 + tid] = spart[tid] + spart[128 + tid];
}

// ---------------- Kernel 3: softmax over S per batch row ----------------
__global__ void softmax_kernel(float* __restrict__ attn_out) {
    int b = blockIdx.x, tid = threadIdx.x;
    __shared__ float red[256];
    float v[8];
    float m = -1e30f;
#pragma unroll
    for (int i = 0; i < 8; i++) {
        v[i] = g_scores[b * NS + tid + 256 * i];
        m = fmaxf(m, v[i]);
    }
    red[tid] = m;
    __syncthreads();
    for (int s = 128; s > 0; s >>= 1) {
        if (tid < s) red[tid] = fmaxf(red[tid], red[tid + s]);
        __syncthreads();
    }
    m = red[0];
    __syncthreads();
    float sum = 0.0f;
#pragma unroll
    for (int i = 0; i < 8; i++) {
        v[i] = __expf(v[i] - m);
        sum += v[i];
    }
    red[tid] = sum;
    __syncthreads();
    for (int s = 128; s > 0; s >>= 1) {
        if (tid < s) red[tid] += red[tid + s];
        __syncthreads();
    }
    float inv = 1.0f / red[0];
#pragma unroll
    for (int i = 0; i < 8; i++)
        attn_out[b * NS + tid + 256 * i] = v[i] * inv;
}

// ---------------- Kernel 4a: context partials over s-chunks ----------------
// Grid (4 dc, 64 b, 4 sc): 1024 CTAs -> better DRAM occupancy than 256.
__global__ void context_part_kernel(const float* __restrict__ enc,
                                    const float* __restrict__ attn) {
    int dc = blockIdx.x, b = blockIdx.y, scch = blockIdx.z;
    int tid = threadIdx.x;
    int lx = tid & 31, ty = tid >> 5;
    __shared__ float att[512];
    __shared__ float4 redc[7][32];
    att[tid]       = attn[b * NS + scch * 512 + tid];
    att[tid + 256] = attn[b * NS + scch * 512 + tid + 256];
    __syncthreads();
    int d0 = dc * 128 + lx * 4;
    const float* basep = enc + (size_t)b * NS * ND + (size_t)scch * 512 * ND + d0;
    float4 acc = {0.0f, 0.0f, 0.0f, 0.0f};
#pragma unroll 4
    for (int s = ty; s < 512; s += 8) {
        float a = att[s];
        float4 v = *reinterpret_cast<const float4*>(basep + (size_t)s * ND);
        acc.x += a * v.x; acc.y += a * v.y;
        acc.z += a * v.z; acc.w += a * v.w;
    }
    if (ty > 0) redc[ty - 1][lx] = acc;
    __syncthreads();
    if (ty == 0) {
#pragma unroll
        for (int i = 0; i < 7; i++) {
            float4 r = redc[i][lx];
            acc.x += r.x; acc.y += r.y; acc.z += r.z; acc.w += r.w;
        }
        *reinterpret_cast<float4*>(&g_cpart[scch][b * ND + d0]) = acc;
    }
}

// ---------------- Kernel 4b: reduce partials ----------------
__global__ void context_reduce_kernel(float* __restrict__ ctx) {
    int b = blockIdx.x, tid = threadIdx.x;
#pragma unroll
    for (int d = tid; d < ND; d += 256)
        ctx[b * ND + d] = g_cpart[0][b * ND + d] + g_cpart[1][b * ND + d] +
                          g_cpart[2][b * ND + d] + g_cpart[3][b * ND + d];
}

extern "C" void kernel_launch(void* const* d_in, const int* in_sizes, int n_in,
                              void* d_out, int out_size) {
    const float* enc = (const float*)d_in[0];
    const float* dec = (const float*)d_in[1];
    const float* W1  = (const float*)d_in[2];
    const float* b1  = (const float*)d_in[3];
    const float* W2  = (const float*)d_in[4];
    const float* b2  = (const float*)d_in[5];
    const float* V   = (const float*)d_in[6];
    // d_in[7] = bv: softmax shift-invariance -> unused.

    float* ctx  = (float*)d_out;             // [64, 512]
    float* attn = (float*)d_out + NB * ND;   // [64, 2048]

    cudaFuncSetAttribute(score_kernel,
                         cudaFuncAttributeMaxDynamicSharedMemorySize,
                         SMEM_BYTES);

    round_w1<<<(ND * NU) / 1024, 256>>>(W1);
    dec_proj_kernel<<<NB, 256>>>(dec, W2, b1, b2);
    score_kernel<<<(NB * NS) / 128, 256, SMEM_BYTES>>>(enc, V);
    softmax_kernel<<<NB, 256>>>(attn);
    context_part_kernel<<<dim3(4, NB, 4), 256>>>(enc, attn);
    context_reduce_kernel<<<NB, 256>>>(ctx);
}